// round 12
// baseline (speedup 1.0000x reference)
#include <cuda_runtime.h>

#define NT    64
#define BATCH 8192

// Per sample: E_w = <Phi| (⊗_{j<=w} O_j) |Phi>,  Phi = CNOT-chain |⊗ phi_j>
// (bond-2 MPS).  O_j = cos^2(t) Z + sin(t)cos(t) Y - sin(t) X, t = params[1][j].
// phi_j = RY(t1) RX(t1) RY(x_j)|0>, t1 = params[0][j].
// Hermitian boundary in trace/difference form, using |f0|^2+|f1|^2 = 1:
//   T = L00+L11, D = L00-L11, P = L01 (complex), Z_j = |f0|^2-|f1|^2,
//   g = f0*conj(f1).
//   E   = T + 4 gr Pr          (= N00+N11; also the emitted expectation)
//   T'  = cc (Z D - 4 gi Pi)
//   D'  = cc E                  <- emission is free
//   N01 = ( gr T + Pr ,  gi D + Z Pi );   P' = (a + i b) N01
// with a = -sin t, b = sin t cos t, cc = cos^2 t.
// Init (T,D,Pr,Pi) = (1,1,0,0); E_{j-1} emitted with wire-j (E pre-update);
// final E_11 = T + 2 Pr.
__global__ void __launch_bounds__(NT)
qexp_kernel(const float* __restrict__ x, const float* __restrict__ params,
            const float* __restrict__ hw, const float* __restrict__ hb,
            float* __restrict__ out)
{
    const int b = blockIdx.x * NT + threadIdx.x;

    // ---- issue ALL loads up front (one memory epoch, MLP ~13) ----
    const float4* xv = (const float4*)(x + b * 12);       // 48B row, 16B aligned
    const float4 xq0 = xv[0], xq1 = xv[1], xq2 = xv[2];
    const float4* pv = (const float4*)params;             // 24 floats (broadcast)
    const float4 p0 = pv[0], p1 = pv[1], p2 = pv[2];
    const float4 p3 = pv[3], p4 = pv[4], p5 = pv[5];
    const float4* wv = (const float4*)hw;                 // 12 floats (broadcast)
    const float4 w0 = wv[0], w1 = wv[1], w2 = wv[2];
    const float bias = hb[0];

    const float xa[12]  = { xq0.x,xq0.y,xq0.z,xq0.w, xq1.x,xq1.y,xq1.z,xq1.w,
                            xq2.x,xq2.y,xq2.z,xq2.w };
    const float th1[12] = { p0.x,p0.y,p0.z,p0.w, p1.x,p1.y,p1.z,p1.w,
                            p2.x,p2.y,p2.z,p2.w };
    const float th2[12] = { p3.x,p3.y,p3.z,p3.w, p4.x,p4.y,p4.z,p4.w,
                            p5.x,p5.y,p5.z,p5.w };
    const float hwa[12] = { w0.x,w0.y,w0.z,w0.w, w1.x,w1.y,w1.z,w1.w,
                            w2.x,w2.y,w2.z,w2.w };

    // ---- per-wire independent precompute (MUFU-pipelined, high ILP) ----
    float Zq[12], Gr[12], Gr4[12], Gi[12], Gi4[12], Oa[12], Ob[12], Oc[12];
    #pragma unroll
    for (int j = 0; j < 12; j++){
        float s1, c1; __sincosf(0.5f * th1[j], &s1, &c1);
        float s2, c2; __sincosf(th2[j], &s2, &c2);        // full angle for O
        Oa[j] = -s2; Ob[j] = s2 * c2; Oc[j] = c2 * c2;
        float sx, cx; __sincosf(0.5f * xa[j], &sx, &cx);
        // phi_j = RY(t1) RX(t1) (cx, sx)
        const float f0r =  c1 * (c1 * cx - s1 * sx);
        const float f0i =  s1 * (s1 * cx - c1 * sx);
        const float f1r =  c1 * (s1 * cx + c1 * sx);
        const float f1i = -s1 * (s1 * sx + c1 * cx);
        const float A = fmaf(f0r, f0r, f0i * f0i);
        const float B = fmaf(f1r, f1r, f1i * f1i);
        Zq[j]  = A - B;                            // |f0|^2 - |f1|^2
        const float gr = fmaf(f0r, f1r,  f0i * f1i);   // Re(f0 conj f1)
        const float gi = fmaf(f0i, f1r, -f0r * f1i);   // Im(f0 conj f1)
        Gr[j] = gr; Gr4[j] = 4.f * gr;
        Gi[j] = gi; Gi4[j] = -4.f * gi;
    }

    // ---- serial sweep in (T, D, Pr, Pi) form ----
    float T = 1.f, D = 1.f, Pr = 0.f, Pi = 0.f;
    float acc = bias;

    #pragma unroll
    for (int j = 0; j < 12; j++){
        const float E = fmaf(Gr4[j], Pr, T);       // = N00+N11 = E_{j-1}

        if (j > 0) acc = fmaf(hwa[j-1], E, acc);

        const float cc = Oc[j];
        const float newT = cc * fmaf(Zq[j], D, Gi4[j] * Pi);
        const float newD = cc * E;
        const float N01r = fmaf(Gr[j], T, Pr);
        const float N01i = fmaf(Gi[j], D, Zq[j] * Pi);
        const float a = Oa[j], bb = Ob[j];
        Pr = fmaf(a, N01r, -bb * N01i);
        Pi = fmaf(a, N01i,  bb * N01r);
        T = newT; D = newD;
    }

    const float E11 = fmaf(2.f, Pr, T);            // empty suffix (X_12 = 1)
    acc = fmaf(hwa[11], E11, acc);

    out[b] = acc;
}

extern "C" void kernel_launch(void* const* d_in, const int* in_sizes, int n_in,
                              void* d_out, int out_size)
{
    const float* x      = (const float*)d_in[0];   // [8192,12]
    const float* params = (const float*)d_in[1];   // [2,12]
    const float* hw     = (const float*)d_in[2];   // [1,12]
    const float* hb     = (const float*)d_in[3];   // [1]
    float* out          = (float*)d_out;           // [8192,1]
    (void)in_sizes; (void)n_in; (void)out_size;

    qexp_kernel<<<BATCH / NT, NT>>>(x, params, hw, hb, out);
}